// round 12
// baseline (speedup 1.0000x reference)
#include <cuda_runtime.h>
#include <cuda_bf16.h>
#include <cstdint>

#define N_NODES 50000
#define N_EDGES 800000
#define D_IN    256
#define D_HID   128
#define D_RAW   16
#define TILE_E  64
#define LN_EPS  1e-5f

static_assert(N_EDGES % TILE_E == 0, "edge tiling assumes exact division");

// ---------------- portable warp-MMA helpers (sm_80+ PTX) -------------------
__device__ __forceinline__ uint32_t smem_to_u32(const void* p) {
    uint32_t a;
    asm("{ .reg .u64 t; cvta.to.shared.u64 t, %1; cvt.u32.u64 %0, t; }"
        : "=r"(a) : "l"(p));
    return a;
}
__device__ __forceinline__ void ldsm_x4(uint32_t* r, uint32_t addr) {
    asm volatile("ldmatrix.sync.aligned.m8n8.x4.shared.b16 {%0,%1,%2,%3}, [%4];"
                 : "=r"(r[0]), "=r"(r[1]), "=r"(r[2]), "=r"(r[3]) : "r"(addr));
}
__device__ __forceinline__ void mma_bf16(float* d, const uint32_t* a,
                                         const uint32_t* b) {
    asm volatile(
        "mma.sync.aligned.m16n8k16.row.col.f32.bf16.bf16.f32 "
        "{%0,%1,%2,%3}, {%4,%5,%6,%7}, {%8,%9}, {%0,%1,%2,%3};"
        : "+f"(d[0]), "+f"(d[1]), "+f"(d[2]), "+f"(d[3])
        : "r"(a[0]), "r"(a[1]), "r"(a[2]), "r"(a[3]), "r"(b[0]), "r"(b[1]));
}
__device__ __forceinline__ void red_v4(float* gptr, float a, float b,
                                       float c, float d) {
    asm volatile("red.global.add.v4.f32 [%0], {%1, %2, %3, %4};"
                 :: "l"(gptr), "f"(a), "f"(b), "f"(c), "f"(d) : "memory");
}

// ---------------- scratch (device globals; no runtime allocation) ----------
__device__ float g_b2l[D_IN];                                 // eb2 @ lew
__device__ __align__(16) __nv_bfloat16 g_Bh[D_IN * D_HID];    // bf16(W2L^T) [n][k]
__device__ __align__(16) __nv_bfloat16 g_W1h[D_IN * D_IN];    // w1^T hi [n][k]
__device__ __align__(16) __nv_bfloat16 g_W1l[D_IN * D_IN];    // w1^T lo
__device__ __align__(16) __nv_bfloat16 g_W2h[D_IN * D_IN];    // w2^T hi
__device__ __align__(16) __nv_bfloat16 g_W2l[D_IN * D_IN];    // w2^T lo
__device__ float g_h[(size_t)N_NODES * D_IN];                 // x + aggr
__device__ int   g_is64;                                      // dtype flag

// ---------------- K-1: detect edge_index dtype ------------------------------
__global__ void detect_idx_kernel(const int* __restrict__ ei32) {
    if (threadIdx.x == 0 && blockIdx.x == 0) {
        int is64 = 1;
        for (int i = 0; i < 64; i++)
            if (ei32[2 * i + 1] != 0) { is64 = 0; break; }
        g_is64 = is64;
    }
}

// ---------------- K0a: fold ew2 @ lew, bf16 hi part -------------------------
__global__ void precompute_kernel(const float* __restrict__ ew2,
                                  const float* __restrict__ lew,
                                  const float* __restrict__ eb2) {
    int idx = blockIdx.x * blockDim.x + threadIdx.x;   // 0..32767
    int k = idx >> 8;      // 0..127 (hid)
    int n = idx & 255;     // 0..255 (out col)
    float s = 0.f;
#pragma unroll 8
    for (int j = 0; j < D_HID; j++)
        s = fmaf(ew2[k * D_HID + j], lew[j * D_IN + n], s);
    g_Bh[n * D_HID + k] = __float2bfloat16(s);
    if (idx < D_IN) {
        float b = 0.f;
        for (int j = 0; j < D_HID; j++)
            b = fmaf(eb2[j], lew[j * D_IN + idx], b);
        g_b2l[idx] = b;
    }
}

// ---------------- K0b: transpose + split both node weights (one launch) -----
__global__ void split_w_kernel(const float* __restrict__ w1,
                               const float* __restrict__ w2) {
    int gidx = blockIdx.x * blockDim.x + threadIdx.x;  // 0..131071
    int which = gidx >> 16;
    int idx = gidx & 65535;
    const float* w = which ? w2 : w1;
    __nv_bfloat16* Wh = which ? g_W2h : g_W1h;
    __nv_bfloat16* Wl = which ? g_W2l : g_W1l;
    int k = idx >> 8, n = idx & 255;
    float v = w[k * D_IN + n];
    __nv_bfloat16 hi = __float2bfloat16(v);
    Wh[n * D_IN + k] = hi;
    Wl[n * D_IN + k] = __float2bfloat16(v - __bfloat162float(hi));
}

// ---------------- K1: g_h = x ----------------------------------------------
__global__ void init_h_kernel(const float* __restrict__ x) {
    const size_t total = (size_t)N_NODES * D_IN / 4;
    const float4* xs = (const float4*)x;
    float4* hs = (float4*)g_h;
    for (size_t i = (size_t)blockIdx.x * blockDim.x + threadIdx.x; i < total;
         i += (size_t)gridDim.x * blockDim.x)
        hs[i] = xs[i];
}

// ---------------- K2: edge kernel (64-edge tiles, 2 CTAs/SM) ----------------
// Unchanged from R11 (proven: 1-term bf16, permuted B, red.v4 epilogue).
#define STRIDE_AB 272
#define OFF_BH   0
#define OFF_A    69632
#define OFF_EW1  87040
#define OFF_RAW  95232
#define OFF_EB1  99328
#define OFF_B2L  99840
#define OFF_LEB  100864
#define OFF_POL  101888
#define OFF_SRC  102144
#define OFF_DST  102400
#define EDGE_SMEM 102656
#define EDGE_THREADS 256
#define EDGE_GRID 296

__global__ __launch_bounds__(EDGE_THREADS, 2)
void edge_kernel(const float* __restrict__ x,
                 const void* __restrict__ ei_raw,
                 const float* __restrict__ ea,
                 const float* __restrict__ ew1,
                 const float* __restrict__ eb1,
                 const float* __restrict__ leb) {
    extern __shared__ char smem[];
    const uint32_t smem_u = smem_to_u32(smem);
    float* s_ew1 = (float*)(smem + OFF_EW1);
    float* s_raw = (float*)(smem + OFF_RAW);
    float* s_eb1 = (float*)(smem + OFF_EB1);
    float* s_b2l = (float*)(smem + OFF_B2L);
    float* s_leb = (float*)(smem + OFF_LEB);
    float* s_pol = (float*)(smem + OFF_POL);
    int*   s_src = (int*)(smem + OFF_SRC);
    int*   s_dst = (int*)(smem + OFF_DST);

    const int tid = threadIdx.x;
    const int wid = tid >> 5;
    const int lane = tid & 31;
    const int is64 = g_is64;
    const long long* ei64 = (const long long*)ei_raw;
    const int*       ei32 = (const int*)ei_raw;

    for (int w = tid; w < 256 * 64; w += EDGE_THREADS) {
        int G = w >> 6, k2 = w & 63;
        int wnb = G >> 6;
        int gl = G & 63;
        int na = 2 * (gl >> 4) + ((gl >> 1) & 1);
        int c  = 2 * ((gl >> 2) & 3) + (gl & 1);
        int n  = wnb * 64 + na * 8 + c;
        *(uint32_t*)(smem + OFF_BH + (uint32_t)n * STRIDE_AB + (uint32_t)k2 * 4u)
            = ((const uint32_t*)g_Bh)[w];
    }
    for (int i = tid; i < D_RAW * D_HID; i += EDGE_THREADS) s_ew1[i] = ew1[i];
    if (tid < D_HID) s_eb1[tid] = eb1[tid];
    if (tid < D_IN) { s_b2l[tid] = g_b2l[tid]; s_leb[tid] = leb[tid]; }
    __syncthreads();

    const int numTiles = N_EDGES / TILE_E;
    const int stride = gridDim.x;

    const int wm = wid & 1;
    const int wn = wid >> 1;
    const uint32_t a_off = (uint32_t)(wm * 32 + (lane & 15)) * STRIDE_AB +
                           (uint32_t)(lane >> 4) * 16u;
    const uint32_t b4_off = (uint32_t)(wn * 64 + ((lane >> 4) & 1) * 8 +
                                       (lane & 7)) * STRIDE_AB +
                            (uint32_t)((lane >> 3) & 1) * 16u;
    const int q  = lane >> 2;

    for (int t = blockIdx.x; t < numTiles; t += stride) {
        {
            const int e0 = t * TILE_E;
            const int er0 = wid * 8;
            for (int i = lane; i < 8 * 17; i += 32) {
                int le = i / 17, c = i % 17;
                float v = ea[(size_t)(e0 + er0 + le) * 17 + c];
                if (c == 0)
                    s_pol[er0 + le] = fminf(fmaxf(v, 0.f), 1.f) + 0.01f;
                else
                    s_raw[(er0 + le) * D_RAW + (c - 1)] = v;
            }
            if (lane < 8) {
                int sv = is64 ? (int)ei64[e0 + er0 + lane]
                              : ei32[e0 + er0 + lane];
                s_src[er0 + lane] = min(max(sv, 0), N_NODES - 1);
            } else if (lane < 16) {
                int l8 = lane - 8;
                int dv = is64 ? (int)ei64[N_EDGES + e0 + er0 + l8]
                              : ei32[N_EDGES + e0 + er0 + l8];
                s_dst[er0 + l8] = min(max(dv, 0), N_NODES - 1);
            }
            __syncwarp();

            const int c0 = lane * 4;
            float4 a4[8];
            float4 eb4 = *(const float4*)&s_eb1[c0];
#pragma unroll
            for (int e = 0; e < 8; e++) a4[e] = eb4;
#pragma unroll
            for (int kb = 0; kb < 4; kb++) {
                float4 w0 = *(const float4*)&s_ew1[(kb * 4 + 0) * D_HID + c0];
                float4 w1 = *(const float4*)&s_ew1[(kb * 4 + 1) * D_HID + c0];
                float4 w2 = *(const float4*)&s_ew1[(kb * 4 + 2) * D_HID + c0];
                float4 w3 = *(const float4*)&s_ew1[(kb * 4 + 3) * D_HID + c0];
#pragma unroll
                for (int e = 0; e < 8; e++) {
                    float4 r = *(const float4*)&s_raw[(er0 + e) * D_RAW + kb * 4];
                    float4 a = a4[e];
                    a.x = fmaf(r.x, w0.x, a.x); a.y = fmaf(r.x, w0.y, a.y);
                    a.z = fmaf(r.x, w0.z, a.z); a.w = fmaf(r.x, w0.w, a.w);
                    a.x = fmaf(r.y, w1.x, a.x); a.y = fmaf(r.y, w1.y, a.y);
                    a.z = fmaf(r.y, w1.z, a.z); a.w = fmaf(r.y, w1.w, a.w);
                    a.x = fmaf(r.z, w2.x, a.x); a.y = fmaf(r.z, w2.y, a.y);
                    a.z = fmaf(r.z, w2.z, a.z); a.w = fmaf(r.z, w2.w, a.w);
                    a.x = fmaf(r.w, w3.x, a.x); a.y = fmaf(r.w, w3.y, a.y);
                    a.z = fmaf(r.w, w3.z, a.z); a.w = fmaf(r.w, w3.w, a.w);
                    a4[e] = a;
                }
            }
            char* ah = smem + OFF_A + (er0 * STRIDE_AB) + lane * 8;
#pragma unroll
            for (int e = 0; e < 8; e++) {
                float4 a = a4[e];
                __nv_bfloat162 h01, h23;
                h01.x = __float2bfloat16(fmaxf(a.x, 0.f));
                h01.y = __float2bfloat16(fmaxf(a.y, 0.f));
                h23.x = __float2bfloat16(fmaxf(a.z, 0.f));
                h23.y = __float2bfloat16(fmaxf(a.w, 0.f));
                *(uint2*)(ah + e * STRIDE_AB) =
                    make_uint2(*(uint32_t*)&h01, *(uint32_t*)&h23);
            }
        }
        __syncthreads();

        float acc[2][8][4];
#pragma unroll
        for (int ma = 0; ma < 2; ma++)
#pragma unroll
            for (int na = 0; na < 8; na++)
#pragma unroll
                for (int r = 0; r < 4; r++) acc[ma][na][r] = 0.f;

        const uint32_t aBase = smem_u + OFF_A;
#pragma unroll
        for (int ks = 0; ks < 8; ks++) {
            const uint32_t ka = (uint32_t)ks * 32u;
            uint32_t ah0[4], ah1[4];
            ldsm_x4(ah0, aBase + a_off + ka);
            ldsm_x4(ah1, aBase + a_off + 16u * STRIDE_AB + ka);
#pragma unroll
            for (int np = 0; np < 4; np++) {
                uint32_t bq[4];
                ldsm_x4(bq, smem_u + OFF_BH + b4_off +
                            (uint32_t)np * 16u * STRIDE_AB + ka);
                mma_bf16(acc[0][2 * np],     ah0, &bq[0]);
                mma_bf16(acc[1][2 * np],     ah1, &bq[0]);
                mma_bf16(acc[0][2 * np + 1], ah0, &bq[2]);
                mma_bf16(acc[1][2 * np + 1], ah1, &bq[2]);
            }
        }

#pragma unroll
        for (int ma = 0; ma < 2; ma++) {
#pragma unroll
            for (int hl = 0; hl < 2; hl++) {
                const int row = wm * 32 + ma * 16 + q + hl * 8;
                const float s = s_pol[row];
                const float* xr = x + (size_t)s_src[row] * D_IN + wn * 64;
                float* hd = g_h + (size_t)s_dst[row] * D_IN + wn * 64;
#pragma unroll
                for (int p = 0; p < 4; p++) {
                    const int cl = p * 16 + (lane & 3) * 4;
                    const int col = wn * 64 + cl;
                    float4 bb = *(const float4*)&s_b2l[col];
                    float4 ll = *(const float4*)&s_leb[col];
                    float4 xv = *(const float4*)(xr + cl);
                    float m0 = fmaxf(
                        fmaf(s, acc[ma][2 * p][hl * 2 + 0] + bb.x, ll.x) + xv.x,
                        0.f);
                    float m1 = fmaxf(
                        fmaf(s, acc[ma][2 * p][hl * 2 + 1] + bb.y, ll.y) + xv.y,
                        0.f);
                    float m2 = fmaxf(
                        fmaf(s, acc[ma][2 * p + 1][hl * 2 + 0] + bb.z, ll.z) +
                            xv.z, 0.f);
                    float m3 = fmaxf(
                        fmaf(s, acc[ma][2 * p + 1][hl * 2 + 1] + bb.w, ll.w) +
                            xv.w, 0.f);
                    red_v4(hd + cl, m0, m1, m2, m3);
                }
            }
        }
        __syncthreads();
    }
}

// ---------------- K3: FUSED node kernel (GEMM1 + LN + GEMM2) ----------------
// A region: [kc:2][split:2][128 rows][272B]  (full k=256 resident)
// B region: [split:2][256 rows][144B]        (one k-64 chunk of W1 or W2)
#define F_A_CH    69632     // per-kc slot (hi+lo)
#define F_A_SPL   34816
#define FOFF_A    0         // 139264
#define FOFF_B    139264    // 73728
#define F_B_SPL   36864
#define FOFF_PART 212992    // 4096
#define FOFF_B1   217088    // 1024
#define FOFF_B2   218112    // 1024
#define FOFF_LNG  219136    // 1024
#define FOFF_LNB  220160    // 1024
#define FUSED_SMEM 221184
#define B_STRIDE  144
#define N_TILES_M ((N_NODES + 127) / 128)   // 391

__global__ __launch_bounds__(512, 1)
void fused_node_kernel(const float* __restrict__ b1,
                       const float* __restrict__ ln_g,
                       const float* __restrict__ ln_b,
                       const float* __restrict__ b2,
                       float* __restrict__ out) {
    extern __shared__ char smem[];
    const uint32_t smem_u = smem_to_u32(smem);
    float* s_part = (float*)(smem + FOFF_PART);
    float* s_b1   = (float*)(smem + FOFF_B1);
    float* s_b2   = (float*)(smem + FOFF_B2);
    float* s_lng  = (float*)(smem + FOFF_LNG);
    float* s_lnb  = (float*)(smem + FOFF_LNB);

    const int tid = threadIdx.x;
    const int wid = tid >> 5;
    const int lane = tid & 31;
    const int r0 = blockIdx.x * 128;

    if (tid < D_IN) {
        s_b1[tid] = b1[tid];  s_b2[tid] = b2[tid];
        s_lng[tid] = ln_g[tid]; s_lnb[tid] = ln_b[tid];
    }

    const int wm = wid & 3;
    const int wn = wid >> 2;
    const uint32_t a_off = (uint32_t)(wm * 32 + (lane & 15)) * STRIDE_AB +
                           (uint32_t)(lane >> 4) * 16u;
    const uint32_t b_off = (uint32_t)(wn * 64 + ((lane >> 4) & 1) * 8 +
                                      (lane & 7)) * B_STRIDE +
                           (uint32_t)((lane >> 3) & 1) * 16u;
    const int q  = lane >> 2;
    const int cp = (lane & 3) * 2;

    // stage full A (g_h rows r0..r0+127, k=0..255, hi/lo)
    for (int i = tid; i < 128 * 64; i += 512) {
        int r = i >> 6, c4 = i & 63;
        int rr = min(r0 + r, N_NODES - 1);
        float4 v = *(const float4*)&g_h[(size_t)rr * D_IN + c4 * 4];
        __nv_bfloat162 h01, h23, l01, l23;
        h01.x = __float2bfloat16(v.x); h01.y = __float2bfloat16(v.y);
        h23.x = __float2bfloat16(v.z); h23.y = __float2bfloat16(v.w);
        l01.x = __float2bfloat16(v.x - __bfloat162float(h01.x));
        l01.y = __float2bfloat16(v.y - __bfloat162float(h01.y));
        l23.x = __float2bfloat16(v.z - __bfloat162float(h23.x));
        l23.y = __float2bfloat16(v.w - __bfloat162float(h23.y));
        uint32_t off = (uint32_t)(c4 >> 5) * F_A_CH + (uint32_t)r * STRIDE_AB +
                       (uint32_t)(c4 & 31) * 8;
        *(uint2*)(smem + FOFF_A + off) =
            make_uint2(*(uint32_t*)&h01, *(uint32_t*)&h23);
        *(uint2*)(smem + FOFF_A + F_A_SPL + off) =
            make_uint2(*(uint32_t*)&l01, *(uint32_t*)&l23);
    }

    // B chunk stager: k-64 chunk g of W (row n, k in [g*64, g*64+64))
    auto stage_B = [&](const __nv_bfloat16* Wh, const __nv_bfloat16* Wl, int g) {
        for (int i = tid; i < 256 * 8; i += 512) {
            int n = i >> 3, c = i & 7;
            const size_t src = (size_t)n * D_IN + g * 64 + c * 8;
            uint32_t dst = (uint32_t)n * B_STRIDE + (uint32_t)c * 16;
            *(uint4*)(smem + FOFF_B + dst) = *(const uint4*)(Wh + src);
            *(uint4*)(smem + FOFF_B + F_B_SPL + dst) = *(const uint4*)(Wl + src);
        }
    };

    float acc[2][8][4];

    // 3-term GEMM over 4 k-64 chunks with B resident per chunk
    auto run_gemm = [&](const __nv_bfloat16* Wh, const __nv_bfloat16* Wl) {
#pragma unroll
        for (int ma = 0; ma < 2; ma++)
#pragma unroll
            for (int na = 0; na < 8; na++)
#pragma unroll
                for (int r = 0; r < 4; r++) acc[ma][na][r] = 0.f;
        for (int g = 0; g < 4; g++) {
            stage_B(Wh, Wl, g);
            __syncthreads();
            const uint32_t aSlot = smem_u + FOFF_A + (uint32_t)(g >> 1) * F_A_CH;
            const uint32_t ain = (uint32_t)(g & 1) * 128u;
#pragma unroll
            for (int ks = 0; ks < 4; ks++) {
                const uint32_t ka = ain + (uint32_t)ks * 32u;
                uint32_t ah0[4], ah1[4], al0[4], al1[4];
                ldsm_x4(ah0, aSlot + a_off + ka);
                ldsm_x4(ah1, aSlot + a_off + 16u * STRIDE_AB + ka);
                ldsm_x4(al0, aSlot + F_A_SPL + a_off + ka);
                ldsm_x4(al1, aSlot + F_A_SPL + a_off + 16u * STRIDE_AB + ka);
                const uint32_t kb = (uint32_t)ks * 32u;
#pragma unroll
                for (int np = 0; np < 4; np++) {
                    uint32_t bh[4], bl[4];
                    const uint32_t bo = b_off + (uint32_t)np * 16u * B_STRIDE + kb;
                    ldsm_x4(bh, smem_u + FOFF_B + bo);
                    ldsm_x4(bl, smem_u + FOFF_B + F_B_SPL + bo);
                    mma_bf16(acc[0][2 * np],     ah0, &bh[0]);
                    mma_bf16(acc[1][2 * np],     ah1, &bh[0]);
                    mma_bf16(acc[0][2 * np],     al0, &bh[0]);
                    mma_bf16(acc[1][2 * np],     al1, &bh[0]);
                    mma_bf16(acc[0][2 * np],     ah0, &bl[0]);
                    mma_bf16(acc[1][2 * np],     ah1, &bl[0]);
                    mma_bf16(acc[0][2 * np + 1], ah0, &bh[2]);
                    mma_bf16(acc[1][2 * np + 1], ah1, &bh[2]);
                    mma_bf16(acc[0][2 * np + 1], al0, &bh[2]);
                    mma_bf16(acc[1][2 * np + 1], al1, &bh[2]);
                    mma_bf16(acc[0][2 * np + 1], ah0, &bl[2]);
                    mma_bf16(acc[1][2 * np + 1], ah1, &bl[2]);
                }
            }
            __syncthreads();
        }
    };

    __syncthreads();          // A staged (and biases)
    run_gemm(g_W1h, g_W1l);   // GEMM1: g_h @ w1

    // ---- bias1 + LayerNorm (in-register, partials via smem) ----
#pragma unroll
    for (int ma = 0; ma < 2; ma++)
#pragma unroll
        for (int na = 0; na < 8; na++)
#pragma unroll
            for (int hl = 0; hl < 2; hl++) {
                acc[ma][na][hl * 2 + 0] += s_b1[wn * 64 + na * 8 + cp];
                acc[ma][na][hl * 2 + 1] += s_b1[wn * 64 + na * 8 + cp + 1];
            }
#pragma unroll
    for (int ma = 0; ma < 2; ma++)
#pragma unroll
        for (int hl = 0; hl < 2; hl++) {
            float s = 0.f, ss = 0.f;
#pragma unroll
            for (int na = 0; na < 8; na++) {
                float v0 = acc[ma][na][hl * 2 + 0];
                float v1 = acc[ma][na][hl * 2 + 1];
                s += v0 + v1;
                ss = fmaf(v0, v0, ss); ss = fmaf(v1, v1, ss);
            }
            s  += __shfl_xor_sync(0xffffffffu, s, 1);
            s  += __shfl_xor_sync(0xffffffffu, s, 2);
            ss += __shfl_xor_sync(0xffffffffu, ss, 1);
            ss += __shfl_xor_sync(0xffffffffu, ss, 2);
            if ((lane & 3) == 0) {
                const int row = wm * 32 + ma * 16 + hl * 8 + q;
                *(float2*)&s_part[row * 8 + wn * 2] = make_float2(s, ss);
            }
        }
    __syncthreads();

    // LN finalize; write bf16 hi/lo of relu(LN(h1)) DIRECTLY into A region
#pragma unroll
    for (int ma = 0; ma < 2; ma++)
#pragma unroll
        for (int hl = 0; hl < 2; hl++) {
            const int row = wm * 32 + ma * 16 + hl * 8 + q;
            float sum = 0.f, ssum = 0.f;
#pragma unroll
            for (int w = 0; w < 4; w++) {
                float2 p = *(const float2*)&s_part[row * 8 + w * 2];
                sum += p.x; ssum += p.y;
            }
            const float mu = sum * (1.f / D_IN);
            const float var = fmaxf(ssum * (1.f / D_IN) - mu * mu, 0.f);
            const float rstd = rsqrtf(var + LN_EPS);
#pragma unroll
            for (int na = 0; na < 8; na++) {
                const int col = wn * 64 + na * 8 + cp;   // even -> 4B aligned
                float o0 = fmaxf(
                    fmaf((acc[ma][na][hl * 2] - mu) * rstd, s_lng[col],
                         s_lnb[col]), 0.f);
                float o1 = fmaxf(
                    fmaf((acc[ma][na][hl * 2 + 1] - mu) * rstd, s_lng[col + 1],
                         s_lnb[col + 1]), 0.f);
                __nv_bfloat162 h, l;
                h.x = __float2bfloat16(o0);
                h.y = __float2bfloat16(o1);
                l.x = __float2bfloat16(o0 - __bfloat162float(h.x));
                l.y = __float2bfloat16(o1 - __bfloat162float(h.y));
                uint32_t off = (uint32_t)(col >> 7) * F_A_CH +
                               (uint32_t)row * STRIDE_AB +
                               (uint32_t)(col & 127) * 2u;
                *(uint32_t*)(smem + FOFF_A + off) = *(uint32_t*)&h;
                *(uint32_t*)(smem + FOFF_A + F_A_SPL + off) = *(uint32_t*)&l;
            }
        }
    __syncthreads();          // A rewrite complete before GEMM2 ldsm

    run_gemm(g_W2h, g_W2l);   // GEMM2: g_t @ w2

    // ---- bias2 + store out ----
#pragma unroll
    for (int ma = 0; ma < 2; ma++)
#pragma unroll
        for (int hl = 0; hl < 2; hl++) {
            const int row = wm * 32 + ma * 16 + hl * 8 + q;
            const int grow = r0 + row;
            if (grow < N_NODES) {
#pragma unroll
                for (int na = 0; na < 8; na++) {
                    const int col = wn * 64 + na * 8 + cp;
                    *(float2*)&out[(size_t)grow * D_IN + col] = make_float2(
                        acc[ma][na][hl * 2 + 0] + s_b2[col],
                        acc[ma][na][hl * 2 + 1] + s_b2[col + 1]);
                }
            }
        }
}

// ---------------- launcher --------------------------------------------------
extern "C" void kernel_launch(void* const* d_in, const int* in_sizes, int n_in,
                              void* d_out, int out_size) {
    const float* x    = (const float*)d_in[0];
    const void*  ei   = d_in[1];
    const float* ea   = (const float*)d_in[2];
    const float* ew1  = (const float*)d_in[3];
    const float* eb1  = (const float*)d_in[4];
    const float* ew2  = (const float*)d_in[5];
    const float* eb2  = (const float*)d_in[6];
    const float* lew  = (const float*)d_in[7];
    const float* leb  = (const float*)d_in[8];
    const float* w1   = (const float*)d_in[9];
    const float* b1   = (const float*)d_in[10];
    const float* ln_g = (const float*)d_in[11];
    const float* ln_b = (const float*)d_in[12];
    const float* w2   = (const float*)d_in[13];
    const float* b2   = (const float*)d_in[14];
    float* out = (float*)d_out;

    cudaFuncSetAttribute(edge_kernel, cudaFuncAttributeMaxDynamicSharedMemorySize,
                         EDGE_SMEM);
    cudaFuncSetAttribute(fused_node_kernel,
                         cudaFuncAttributeMaxDynamicSharedMemorySize, FUSED_SMEM);

    detect_idx_kernel<<<1, 32>>>((const int*)ei);
    precompute_kernel<<<128, 256>>>(ew2, lew, eb2);
    split_w_kernel<<<512, 256>>>(w1, w2);
    init_h_kernel<<<1184, 256>>>(x);
    edge_kernel<<<EDGE_GRID, EDGE_THREADS, EDGE_SMEM>>>(x, ei, ea, ew1, eb1, leb);
    fused_node_kernel<<<N_TILES_M, 512, FUSED_SMEM>>>(b1, ln_g, ln_b, b2, out);
}

// round 13
// speedup vs baseline: 1.0277x; 1.0277x over previous
#include <cuda_runtime.h>
#include <cuda_bf16.h>
#include <cstdint>

#define N_NODES 50000
#define N_EDGES 800000
#define D_IN    256
#define D_HID   128
#define D_RAW   16
#define TILE_E  64
#define LN_EPS  1e-5f

static_assert(N_EDGES % TILE_E == 0, "edge tiling assumes exact division");

// ---------------- portable warp-MMA helpers (sm_80+ PTX) -------------------
__device__ __forceinline__ uint32_t smem_to_u32(const void* p) {
    uint32_t a;
    asm("{ .reg .u64 t; cvta.to.shared.u64 t, %1; cvt.u32.u64 %0, t; }"
        : "=r"(a) : "l"(p));
    return a;
}
__device__ __forceinline__ void ldsm_x4(uint32_t* r, uint32_t addr) {
    asm volatile("ldmatrix.sync.aligned.m8n8.x4.shared.b16 {%0,%1,%2,%3}, [%4];"
                 : "=r"(r[0]), "=r"(r[1]), "=r"(r[2]), "=r"(r[3]) : "r"(addr));
}
__device__ __forceinline__ void mma_bf16(float* d, const uint32_t* a,
                                         const uint32_t* b) {
    asm volatile(
        "mma.sync.aligned.m16n8k16.row.col.f32.bf16.bf16.f32 "
        "{%0,%1,%2,%3}, {%4,%5,%6,%7}, {%8,%9}, {%0,%1,%2,%3};"
        : "+f"(d[0]), "+f"(d[1]), "+f"(d[2]), "+f"(d[3])
        : "r"(a[0]), "r"(a[1]), "r"(a[2]), "r"(a[3]), "r"(b[0]), "r"(b[1]));
}
__device__ __forceinline__ void red_v4(float* gptr, float a, float b,
                                       float c, float d) {
    asm volatile("red.global.add.v4.f32 [%0], {%1, %2, %3, %4};"
                 :: "l"(gptr), "f"(a), "f"(b), "f"(c), "f"(d) : "memory");
}

// ---------------- scratch (device globals; no runtime allocation) ----------
__device__ float g_b2l[D_IN];                                 // eb2 @ lew
__device__ __align__(16) __nv_bfloat16 g_Bh[D_IN * D_HID];    // bf16(W2L^T) [n][k]
__device__ __align__(16) __nv_bfloat16 g_W1h[D_IN * D_IN];    // w1^T hi [n][k]
__device__ __align__(16) __nv_bfloat16 g_W1l[D_IN * D_IN];    // w1^T lo
__device__ __align__(16) __nv_bfloat16 g_W2h[D_IN * D_IN];    // w2^T hi
__device__ __align__(16) __nv_bfloat16 g_W2l[D_IN * D_IN];    // w2^T lo
__device__ float g_h[(size_t)N_NODES * D_IN];                 // aggr (atomic)
__device__ float g_t[(size_t)N_NODES * D_IN];                 // relu(LN(h@w1+b1))
__device__ int   g_is64;                                      // dtype flag

// ---------------- K-1: detect edge_index dtype ------------------------------
__global__ void detect_idx_kernel(const int* __restrict__ ei32) {
    if (threadIdx.x == 0 && blockIdx.x == 0) {
        int is64 = 1;
        for (int i = 0; i < 64; i++)
            if (ei32[2 * i + 1] != 0) { is64 = 0; break; }
        g_is64 = is64;
    }
}

// ---------------- K0a: fold ew2 @ lew, bf16 hi part -------------------------
__global__ void precompute_kernel(const float* __restrict__ ew2,
                                  const float* __restrict__ lew,
                                  const float* __restrict__ eb2) {
    int idx = blockIdx.x * blockDim.x + threadIdx.x;   // 0..32767
    int k = idx >> 8;      // 0..127 (hid)
    int n = idx & 255;     // 0..255 (out col)
    float s = 0.f;
#pragma unroll 8
    for (int j = 0; j < D_HID; j++)
        s = fmaf(ew2[k * D_HID + j], lew[j * D_IN + n], s);
    g_Bh[n * D_HID + k] = __float2bfloat16(s);
    if (idx < D_IN) {
        float b = 0.f;
        for (int j = 0; j < D_HID; j++)
            b = fmaf(eb2[j], lew[j * D_IN + idx], b);
        g_b2l[idx] = b;
    }
}

// ---------------- K0b: transpose + split both node weights (one launch) -----
__global__ void split_w_kernel(const float* __restrict__ w1,
                               const float* __restrict__ w2) {
    int gidx = blockIdx.x * blockDim.x + threadIdx.x;  // 0..131071
    int which = gidx >> 16;
    int idx = gidx & 65535;
    const float* w = which ? w2 : w1;
    __nv_bfloat16* Wh = which ? g_W2h : g_W1h;
    __nv_bfloat16* Wl = which ? g_W2l : g_W1l;
    int k = idx >> 8, n = idx & 255;
    float v = w[k * D_IN + n];
    __nv_bfloat16 hi = __float2bfloat16(v);
    Wh[n * D_IN + k] = hi;
    Wl[n * D_IN + k] = __float2bfloat16(v - __bfloat162float(hi));
}

// ---------------- K1: g_h = 0 (write-only; x folded into node1) -------------
__global__ void zero_h_kernel() {
    const size_t total = (size_t)N_NODES * D_IN / 4;
    float4* hs = (float4*)g_h;
    const float4 z = make_float4(0.f, 0.f, 0.f, 0.f);
    for (size_t i = (size_t)blockIdx.x * blockDim.x + threadIdx.x; i < total;
         i += (size_t)gridDim.x * blockDim.x)
        hs[i] = z;
}

// ---------------- K2: edge kernel (64-edge tiles, 2 CTAs/SM) ----------------
// Unchanged from R11 (proven: 1-term bf16, permuted B, red.v4 epilogue).
#define STRIDE_AB 272
#define OFF_BH   0
#define OFF_A    69632
#define OFF_EW1  87040
#define OFF_RAW  95232
#define OFF_EB1  99328
#define OFF_B2L  99840
#define OFF_LEB  100864
#define OFF_POL  101888
#define OFF_SRC  102144
#define OFF_DST  102400
#define EDGE_SMEM 102656
#define EDGE_THREADS 256
#define EDGE_GRID 296

__global__ __launch_bounds__(EDGE_THREADS, 2)
void edge_kernel(const float* __restrict__ x,
                 const void* __restrict__ ei_raw,
                 const float* __restrict__ ea,
                 const float* __restrict__ ew1,
                 const float* __restrict__ eb1,
                 const float* __restrict__ leb) {
    extern __shared__ char smem[];
    const uint32_t smem_u = smem_to_u32(smem);
    float* s_ew1 = (float*)(smem + OFF_EW1);
    float* s_raw = (float*)(smem + OFF_RAW);
    float* s_eb1 = (float*)(smem + OFF_EB1);
    float* s_b2l = (float*)(smem + OFF_B2L);
    float* s_leb = (float*)(smem + OFF_LEB);
    float* s_pol = (float*)(smem + OFF_POL);
    int*   s_src = (int*)(smem + OFF_SRC);
    int*   s_dst = (int*)(smem + OFF_DST);

    const int tid = threadIdx.x;
    const int wid = tid >> 5;
    const int lane = tid & 31;
    const int is64 = g_is64;
    const long long* ei64 = (const long long*)ei_raw;
    const int*       ei32 = (const int*)ei_raw;

    for (int w = tid; w < 256 * 64; w += EDGE_THREADS) {
        int G = w >> 6, k2 = w & 63;
        int wnb = G >> 6;
        int gl = G & 63;
        int na = 2 * (gl >> 4) + ((gl >> 1) & 1);
        int c  = 2 * ((gl >> 2) & 3) + (gl & 1);
        int n  = wnb * 64 + na * 8 + c;
        *(uint32_t*)(smem + OFF_BH + (uint32_t)n * STRIDE_AB + (uint32_t)k2 * 4u)
            = ((const uint32_t*)g_Bh)[w];
    }
    for (int i = tid; i < D_RAW * D_HID; i += EDGE_THREADS) s_ew1[i] = ew1[i];
    if (tid < D_HID) s_eb1[tid] = eb1[tid];
    if (tid < D_IN) { s_b2l[tid] = g_b2l[tid]; s_leb[tid] = leb[tid]; }
    __syncthreads();

    const int numTiles = N_EDGES / TILE_E;
    const int stride = gridDim.x;

    const int wm = wid & 1;
    const int wn = wid >> 1;
    const uint32_t a_off = (uint32_t)(wm * 32 + (lane & 15)) * STRIDE_AB +
                           (uint32_t)(lane >> 4) * 16u;
    const uint32_t b4_off = (uint32_t)(wn * 64 + ((lane >> 4) & 1) * 8 +
                                       (lane & 7)) * STRIDE_AB +
                            (uint32_t)((lane >> 3) & 1) * 16u;
    const int q  = lane >> 2;

    for (int t = blockIdx.x; t < numTiles; t += stride) {
        {
            const int e0 = t * TILE_E;
            const int er0 = wid * 8;
            for (int i = lane; i < 8 * 17; i += 32) {
                int le = i / 17, c = i % 17;
                float v = ea[(size_t)(e0 + er0 + le) * 17 + c];
                if (c == 0)
                    s_pol[er0 + le] = fminf(fmaxf(v, 0.f), 1.f) + 0.01f;
                else
                    s_raw[(er0 + le) * D_RAW + (c - 1)] = v;
            }
            if (lane < 8) {
                int sv = is64 ? (int)ei64[e0 + er0 + lane]
                              : ei32[e0 + er0 + lane];
                s_src[er0 + lane] = min(max(sv, 0), N_NODES - 1);
            } else if (lane < 16) {
                int l8 = lane - 8;
                int dv = is64 ? (int)ei64[N_EDGES + e0 + er0 + l8]
                              : ei32[N_EDGES + e0 + er0 + l8];
                s_dst[er0 + l8] = min(max(dv, 0), N_NODES - 1);
            }
            __syncwarp();

            const int c0 = lane * 4;
            float4 a4[8];
            float4 eb4 = *(const float4*)&s_eb1[c0];
#pragma unroll
            for (int e = 0; e < 8; e++) a4[e] = eb4;
#pragma unroll
            for (int kb = 0; kb < 4; kb++) {
                float4 w0 = *(const float4*)&s_ew1[(kb * 4 + 0) * D_HID + c0];
                float4 w1 = *(const float4*)&s_ew1[(kb * 4 + 1) * D_HID + c0];
                float4 w2 = *(const float4*)&s_ew1[(kb * 4 + 2) * D_HID + c0];
                float4 w3 = *(const float4*)&s_ew1[(kb * 4 + 3) * D_HID + c0];
#pragma unroll
                for (int e = 0; e < 8; e++) {
                    float4 r = *(const float4*)&s_raw[(er0 + e) * D_RAW + kb * 4];
                    float4 a = a4[e];
                    a.x = fmaf(r.x, w0.x, a.x); a.y = fmaf(r.x, w0.y, a.y);
                    a.z = fmaf(r.x, w0.z, a.z); a.w = fmaf(r.x, w0.w, a.w);
                    a.x = fmaf(r.y, w1.x, a.x); a.y = fmaf(r.y, w1.y, a.y);
                    a.z = fmaf(r.y, w1.z, a.z); a.w = fmaf(r.y, w1.w, a.w);
                    a.x = fmaf(r.z, w2.x, a.x); a.y = fmaf(r.z, w2.y, a.y);
                    a.z = fmaf(r.z, w2.z, a.z); a.w = fmaf(r.z, w2.w, a.w);
                    a.x = fmaf(r.w, w3.x, a.x); a.y = fmaf(r.w, w3.y, a.y);
                    a.z = fmaf(r.w, w3.z, a.z); a.w = fmaf(r.w, w3.w, a.w);
                    a4[e] = a;
                }
            }
            char* ah = smem + OFF_A + (er0 * STRIDE_AB) + lane * 8;
#pragma unroll
            for (int e = 0; e < 8; e++) {
                float4 a = a4[e];
                __nv_bfloat162 h01, h23;
                h01.x = __float2bfloat16(fmaxf(a.x, 0.f));
                h01.y = __float2bfloat16(fmaxf(a.y, 0.f));
                h23.x = __float2bfloat16(fmaxf(a.z, 0.f));
                h23.y = __float2bfloat16(fmaxf(a.w, 0.f));
                *(uint2*)(ah + e * STRIDE_AB) =
                    make_uint2(*(uint32_t*)&h01, *(uint32_t*)&h23);
            }
        }
        __syncthreads();

        float acc[2][8][4];
#pragma unroll
        for (int ma = 0; ma < 2; ma++)
#pragma unroll
            for (int na = 0; na < 8; na++)
#pragma unroll
                for (int r = 0; r < 4; r++) acc[ma][na][r] = 0.f;

        const uint32_t aBase = smem_u + OFF_A;
#pragma unroll
        for (int ks = 0; ks < 8; ks++) {
            const uint32_t ka = (uint32_t)ks * 32u;
            uint32_t ah0[4], ah1[4];
            ldsm_x4(ah0, aBase + a_off + ka);
            ldsm_x4(ah1, aBase + a_off + 16u * STRIDE_AB + ka);
#pragma unroll
            for (int np = 0; np < 4; np++) {
                uint32_t bq[4];
                ldsm_x4(bq, smem_u + OFF_BH + b4_off +
                            (uint32_t)np * 16u * STRIDE_AB + ka);
                mma_bf16(acc[0][2 * np],     ah0, &bq[0]);
                mma_bf16(acc[1][2 * np],     ah1, &bq[0]);
                mma_bf16(acc[0][2 * np + 1], ah0, &bq[2]);
                mma_bf16(acc[1][2 * np + 1], ah1, &bq[2]);
            }
        }

#pragma unroll
        for (int ma = 0; ma < 2; ma++) {
#pragma unroll
            for (int hl = 0; hl < 2; hl++) {
                const int row = wm * 32 + ma * 16 + q + hl * 8;
                const float s = s_pol[row];
                const float* xr = x + (size_t)s_src[row] * D_IN + wn * 64;
                float* hd = g_h + (size_t)s_dst[row] * D_IN + wn * 64;
#pragma unroll
                for (int p = 0; p < 4; p++) {
                    const int cl = p * 16 + (lane & 3) * 4;
                    const int col = wn * 64 + cl;
                    float4 bb = *(const float4*)&s_b2l[col];
                    float4 ll = *(const float4*)&s_leb[col];
                    float4 xv = *(const float4*)(xr + cl);
                    float m0 = fmaxf(
                        fmaf(s, acc[ma][2 * p][hl * 2 + 0] + bb.x, ll.x) + xv.x,
                        0.f);
                    float m1 = fmaxf(
                        fmaf(s, acc[ma][2 * p][hl * 2 + 1] + bb.y, ll.y) + xv.y,
                        0.f);
                    float m2 = fmaxf(
                        fmaf(s, acc[ma][2 * p + 1][hl * 2 + 0] + bb.z, ll.z) +
                            xv.z, 0.f);
                    float m3 = fmaxf(
                        fmaf(s, acc[ma][2 * p + 1][hl * 2 + 1] + bb.w, ll.w) +
                            xv.w, 0.f);
                    red_v4(hd + cl, m0, m1, m2, m3);
                }
            }
        }
        __syncthreads();
    }
}

// ---------------- node GEMM kernels (HMMA, 3-term bf16 emulation) ----------
#define NOFF_BH   0          // B hi chunk [256n][272B]
#define NOFF_BL   69632
#define NOFF_AH   139264     // A hi chunk [128m][272B]
#define NOFF_AL   174080
#define NOFF_PART 208896     // [128][4][2] f32 partial sums (node1 LN)
#define NOFF_B    212992     // bias 256 f
#define NOFF_LNG  214016
#define NOFF_LNB  215040
#define NODE_SMEM 216064
#define N_TILES_M ((N_NODES + 127) / 128)   // 391

// WITH_LN also means: A = Asrc + Xadd (x folded into node1 staging).
template <bool WITH_LN>
__device__ __forceinline__ void node_gemm_body(
    const float* __restrict__ Asrc, const float* __restrict__ Xadd,
    const __nv_bfloat16* __restrict__ Wh,
    const __nv_bfloat16* __restrict__ Wl, const float* __restrict__ bias,
    const float* __restrict__ ln_g, const float* __restrict__ ln_b,
    float* __restrict__ Dst) {
    extern __shared__ char smem[];
    const uint32_t smem_u = smem_to_u32(smem);
    float* s_part = (float*)(smem + NOFF_PART);
    float* s_b    = (float*)(smem + NOFF_B);
    float* s_lng  = (float*)(smem + NOFF_LNG);
    float* s_lnb  = (float*)(smem + NOFF_LNB);

    const int tid = threadIdx.x;
    const int wid = tid >> 5;
    const int lane = tid & 31;
    const int r0 = blockIdx.x * 128;

    if (tid < D_IN) {
        s_b[tid] = bias[tid];
        if (WITH_LN) { s_lng[tid] = ln_g[tid]; s_lnb[tid] = ln_b[tid]; }
    }

    const int wm = wid & 3;
    const int wn = wid >> 2;
    const uint32_t a_off = (uint32_t)(wm * 32 + (lane & 15)) * STRIDE_AB +
                           (uint32_t)(lane >> 4) * 16u;
    const uint32_t b4_off = (uint32_t)(wn * 64 + ((lane >> 4) & 1) * 8 +
                                       (lane & 7)) * STRIDE_AB +
                            (uint32_t)((lane >> 3) & 1) * 16u;
    const int q  = lane >> 2;
    const int cp = (lane & 3) * 2;

    float acc[2][8][4];
#pragma unroll
    for (int ma = 0; ma < 2; ma++)
#pragma unroll
        for (int na = 0; na < 8; na++)
#pragma unroll
            for (int r = 0; r < 4; r++) acc[ma][na][r] = 0.f;

    for (int kc = 0; kc < 2; kc++) {
        for (int i = tid; i < 256 * 16; i += 512) {
            int n = i >> 4, c = i & 15;
            const size_t src = (size_t)n * D_IN + kc * 128 + c * 8;
            *(uint4*)(smem + NOFF_BH + (uint32_t)n * STRIDE_AB + c * 16) =
                *(const uint4*)(Wh + src);
            *(uint4*)(smem + NOFF_BL + (uint32_t)n * STRIDE_AB + c * 16) =
                *(const uint4*)(Wl + src);
        }
        for (int i = tid; i < 128 * 32; i += 512) {
            int r = i >> 5, c4 = i & 31;
            int rr = min(r0 + r, N_NODES - 1);
            const size_t src = (size_t)rr * D_IN + kc * 128 + c4 * 4;
            float4 v = *(const float4*)&Asrc[src];
            if (WITH_LN) {
                float4 xv = *(const float4*)&Xadd[src];
                v.x += xv.x; v.y += xv.y; v.z += xv.z; v.w += xv.w;
            }
            __nv_bfloat162 h01, h23, l01, l23;
            h01.x = __float2bfloat16(v.x); h01.y = __float2bfloat16(v.y);
            h23.x = __float2bfloat16(v.z); h23.y = __float2bfloat16(v.w);
            l01.x = __float2bfloat16(v.x - __bfloat162float(h01.x));
            l01.y = __float2bfloat16(v.y - __bfloat162float(h01.y));
            l23.x = __float2bfloat16(v.z - __bfloat162float(h23.x));
            l23.y = __float2bfloat16(v.w - __bfloat162float(h23.y));
            uint32_t off = (uint32_t)r * STRIDE_AB + c4 * 8;
            *(uint2*)(smem + NOFF_AH + off) =
                make_uint2(*(uint32_t*)&h01, *(uint32_t*)&h23);
            *(uint2*)(smem + NOFF_AL + off) =
                make_uint2(*(uint32_t*)&l01, *(uint32_t*)&l23);
        }
        __syncthreads();

#pragma unroll
        for (int ks = 0; ks < 8; ks++) {
            const uint32_t ka = (uint32_t)ks * 32u;
            uint32_t ah0[4], ah1[4], al0[4], al1[4];
            ldsm_x4(ah0, smem_u + NOFF_AH + a_off + ka);
            ldsm_x4(ah1, smem_u + NOFF_AH + a_off + 16u * STRIDE_AB + ka);
            ldsm_x4(al0, smem_u + NOFF_AL + a_off + ka);
            ldsm_x4(al1, smem_u + NOFF_AL + a_off + 16u * STRIDE_AB + ka);
#pragma unroll
            for (int np = 0; np < 4; np++) {
                uint32_t bh[4], bl[4];
                const uint32_t bo = b4_off + (uint32_t)np * 16u * STRIDE_AB + ka;
                ldsm_x4(bh, smem_u + NOFF_BH + bo);
                ldsm_x4(bl, smem_u + NOFF_BL + bo);
                mma_bf16(acc[0][2 * np],     ah0, &bh[0]);
                mma_bf16(acc[1][2 * np],     ah1, &bh[0]);
                mma_bf16(acc[0][2 * np],     al0, &bh[0]);
                mma_bf16(acc[1][2 * np],     al1, &bh[0]);
                mma_bf16(acc[0][2 * np],     ah0, &bl[0]);
                mma_bf16(acc[1][2 * np],     ah1, &bl[0]);
                mma_bf16(acc[0][2 * np + 1], ah0, &bh[2]);
                mma_bf16(acc[1][2 * np + 1], ah1, &bh[2]);
                mma_bf16(acc[0][2 * np + 1], al0, &bh[2]);
                mma_bf16(acc[1][2 * np + 1], al1, &bh[2]);
                mma_bf16(acc[0][2 * np + 1], ah0, &bl[2]);
                mma_bf16(acc[1][2 * np + 1], ah1, &bl[2]);
            }
        }
        __syncthreads();
    }

    float bcol[8][2];
#pragma unroll
    for (int na = 0; na < 8; na++) {
        bcol[na][0] = s_b[wn * 64 + na * 8 + cp];
        bcol[na][1] = s_b[wn * 64 + na * 8 + cp + 1];
    }
#pragma unroll
    for (int ma = 0; ma < 2; ma++)
#pragma unroll
        for (int na = 0; na < 8; na++)
#pragma unroll
            for (int hl = 0; hl < 2; hl++) {
                acc[ma][na][hl * 2 + 0] += bcol[na][0];
                acc[ma][na][hl * 2 + 1] += bcol[na][1];
            }

    if (WITH_LN) {
#pragma unroll
        for (int ma = 0; ma < 2; ma++)
#pragma unroll
            for (int hl = 0; hl < 2; hl++) {
                float s = 0.f, ss = 0.f;
#pragma unroll
                for (int na = 0; na < 8; na++) {
                    float v0 = acc[ma][na][hl * 2 + 0];
                    float v1 = acc[ma][na][hl * 2 + 1];
                    s += v0 + v1;
                    ss = fmaf(v0, v0, ss); ss = fmaf(v1, v1, ss);
                }
                s  += __shfl_xor_sync(0xffffffffu, s, 1);
                s  += __shfl_xor_sync(0xffffffffu, s, 2);
                ss += __shfl_xor_sync(0xffffffffu, ss, 1);
                ss += __shfl_xor_sync(0xffffffffu, ss, 2);
                if ((lane & 3) == 0) {
                    const int row = wm * 32 + ma * 16 + hl * 8 + q;
                    *(float2*)&s_part[row * 8 + wn * 2] = make_float2(s, ss);
                }
            }
        __syncthreads();

#pragma unroll
        for (int ma = 0; ma < 2; ma++)
#pragma unroll
            for (int hl = 0; hl < 2; hl++) {
                const int row = wm * 32 + ma * 16 + hl * 8 + q;
                float sum = 0.f, ssum = 0.f;
#pragma unroll
                for (int w = 0; w < 4; w++) {
                    float2 p = *(const float2*)&s_part[row * 8 + w * 2];
                    sum += p.x; ssum += p.y;
                }
                const float mu = sum * (1.f / D_IN);
                const float var =
                    fmaxf(ssum * (1.f / D_IN) - mu * mu, 0.f);
                const float rstd = rsqrtf(var + LN_EPS);
                const int grow = r0 + row;
                if (grow < N_NODES) {
#pragma unroll
                    for (int na = 0; na < 8; na++) {
                        const int col = wn * 64 + na * 8 + cp;
                        float g0 = s_lng[col], g1 = s_lng[col + 1];
                        float l0 = s_lnb[col], l1 = s_lnb[col + 1];
                        float o0 = fmaxf(
                            fmaf((acc[ma][na][hl * 2] - mu) * rstd, g0, l0), 0.f);
                        float o1 = fmaxf(
                            fmaf((acc[ma][na][hl * 2 + 1] - mu) * rstd, g1, l1),
                            0.f);
                        *(float2*)&Dst[(size_t)grow * D_IN + col] =
                            make_float2(o0, o1);
                    }
                }
            }
    } else {
#pragma unroll
        for (int ma = 0; ma < 2; ma++)
#pragma unroll
            for (int hl = 0; hl < 2; hl++) {
                const int row = wm * 32 + ma * 16 + hl * 8 + q;
                const int grow = r0 + row;
                if (grow < N_NODES) {
#pragma unroll
                    for (int na = 0; na < 8; na++) {
                        const int col = wn * 64 + na * 8 + cp;
                        *(float2*)&Dst[(size_t)grow * D_IN + col] =
                            make_float2(acc[ma][na][hl * 2],
                                        acc[ma][na][hl * 2 + 1]);
                    }
                }
            }
    }
}

__global__ __launch_bounds__(512, 1)
void node1_kernel(const float* __restrict__ x, const float* __restrict__ b1,
                  const float* __restrict__ ln_g,
                  const float* __restrict__ ln_b) {
    node_gemm_body<true>(g_h, x, g_W1h, g_W1l, b1, ln_g, ln_b, g_t);
}

__global__ __launch_bounds__(512, 1)
void node2_kernel(const float* __restrict__ b2, float* __restrict__ out) {
    node_gemm_body<false>(g_t, nullptr, g_W2h, g_W2l, b2, nullptr, nullptr, out);
}

// ---------------- launcher --------------------------------------------------
extern "C" void kernel_launch(void* const* d_in, const int* in_sizes, int n_in,
                              void* d_out, int out_size) {
    const float* x    = (const float*)d_in[0];
    const void*  ei   = d_in[1];
    const float* ea   = (const float*)d_in[2];
    const float* ew1  = (const float*)d_in[3];
    const float* eb1  = (const float*)d_in[4];
    const float* ew2  = (const float*)d_in[5];
    const float* eb2  = (const float*)d_in[6];
    const float* lew  = (const float*)d_in[7];
    const float* leb  = (const float*)d_in[8];
    const float* w1   = (const float*)d_in[9];
    const float* b1   = (const float*)d_in[10];
    const float* ln_g = (const float*)d_in[11];
    const float* ln_b = (const float*)d_in[12];
    const float* w2   = (const float*)d_in[13];
    const float* b2   = (const float*)d_in[14];
    float* out = (float*)d_out;

    cudaFuncSetAttribute(edge_kernel, cudaFuncAttributeMaxDynamicSharedMemorySize,
                         EDGE_SMEM);
    cudaFuncSetAttribute(node1_kernel, cudaFuncAttributeMaxDynamicSharedMemorySize,
                         NODE_SMEM);
    cudaFuncSetAttribute(node2_kernel, cudaFuncAttributeMaxDynamicSharedMemorySize,
                         NODE_SMEM);

    detect_idx_kernel<<<1, 32>>>((const int*)ei);
    precompute_kernel<<<128, 256>>>(ew2, lew, eb2);
    split_w_kernel<<<512, 256>>>(w1, w2);
    zero_h_kernel<<<1184, 256>>>();
    edge_kernel<<<EDGE_GRID, EDGE_THREADS, EDGE_SMEM>>>(x, ei, ea, ew1, eb1, leb);
    node1_kernel<<<N_TILES_M, 512, NODE_SMEM>>>(x, b1, ln_g, ln_b);
    node2_kernel<<<N_TILES_M, 512, NODE_SMEM>>>(b2, out);
}

// round 14
// speedup vs baseline: 1.0421x; 1.0140x over previous
#include <cuda_runtime.h>
#include <cuda_bf16.h>
#include <cstdint>

#define N_NODES 50000
#define N_EDGES 800000
#define D_IN    256
#define D_HID   128
#define D_RAW   16
#define TILE_E  64
#define LN_EPS  1e-5f

static_assert(N_EDGES % TILE_E == 0, "edge tiling assumes exact division");

// ---------------- portable warp-MMA helpers (sm_80+ PTX) -------------------
__device__ __forceinline__ uint32_t smem_to_u32(const void* p) {
    uint32_t a;
    asm("{ .reg .u64 t; cvta.to.shared.u64 t, %1; cvt.u32.u64 %0, t; }"
        : "=r"(a) : "l"(p));
    return a;
}
__device__ __forceinline__ void ldsm_x4(uint32_t* r, uint32_t addr) {
    asm volatile("ldmatrix.sync.aligned.m8n8.x4.shared.b16 {%0,%1,%2,%3}, [%4];"
                 : "=r"(r[0]), "=r"(r[1]), "=r"(r[2]), "=r"(r[3]) : "r"(addr));
}
__device__ __forceinline__ void mma_bf16(float* d, const uint32_t* a,
                                         const uint32_t* b) {
    asm volatile(
        "mma.sync.aligned.m16n8k16.row.col.f32.bf16.bf16.f32 "
        "{%0,%1,%2,%3}, {%4,%5,%6,%7}, {%8,%9}, {%0,%1,%2,%3};"
        : "+f"(d[0]), "+f"(d[1]), "+f"(d[2]), "+f"(d[3])
        : "r"(a[0]), "r"(a[1]), "r"(a[2]), "r"(a[3]), "r"(b[0]), "r"(b[1]));
}
__device__ __forceinline__ void red_v4(float* gptr, float a, float b,
                                       float c, float d) {
    asm volatile("red.global.add.v4.f32 [%0], {%1, %2, %3, %4};"
                 :: "l"(gptr), "f"(a), "f"(b), "f"(c), "f"(d) : "memory");
}

// ---------------- scratch (device globals; no runtime allocation) ----------
__device__ float g_b2l[D_IN];                                 // eb2 @ lew
__device__ __align__(16) __nv_bfloat16 g_Bh[D_IN * D_HID];    // bf16(W2L^T) [n][k]
__device__ __align__(16) __nv_bfloat16 g_W1h[D_IN * D_IN];    // w1^T hi [n][k]
__device__ __align__(16) __nv_bfloat16 g_W1l[D_IN * D_IN];    // w1^T lo
__device__ __align__(16) __nv_bfloat16 g_W2h[D_IN * D_IN];    // w2^T hi
__device__ __align__(16) __nv_bfloat16 g_W2l[D_IN * D_IN];    // w2^T lo
__device__ float g_h[(size_t)N_NODES * D_IN];                 // aggr (atomic)
__device__ float g_t[(size_t)N_NODES * D_IN];                 // relu(LN(h@w1+b1))
__device__ int   g_is64;                                      // dtype flag

// ---------------- K0: fused prep (detect + precompute + split + zero) -------
// blocks 0..127   : W2L fold -> g_Bh, g_b2l       (idx = b*256+tid, 32768)
// blocks 128..639 : w1/w2 transpose+split         (gidx = (b-128)*256+tid)
// block 0, tid 0  : edge_index dtype detect
// ALL blocks      : grid-strided zero of g_h
#define PREP_GRID 1184
__global__ void prep_kernel(const int* __restrict__ ei32,
                            const float* __restrict__ ew2,
                            const float* __restrict__ lew,
                            const float* __restrict__ eb2,
                            const float* __restrict__ w1,
                            const float* __restrict__ w2) {
    const int b = blockIdx.x;
    const int tid = threadIdx.x;

    if (b == 0 && tid == 0) {
        int is64 = 1;
        for (int i = 0; i < 64; i++)
            if (ei32[2 * i + 1] != 0) { is64 = 0; break; }
        g_is64 = is64;
    }

    if (b < 128) {
        // precompute: fold ew2 @ lew, bf16 hi; g_b2l
        int idx = b * 256 + tid;          // 0..32767
        int k = idx >> 8;                 // 0..127
        int n = idx & 255;                // 0..255
        float s = 0.f;
#pragma unroll 8
        for (int j = 0; j < D_HID; j++)
            s = fmaf(ew2[k * D_HID + j], lew[j * D_IN + n], s);
        g_Bh[n * D_HID + k] = __float2bfloat16(s);
        if (idx < D_IN) {
            float bb = 0.f;
            for (int j = 0; j < D_HID; j++)
                bb = fmaf(eb2[j], lew[j * D_IN + idx], bb);
            g_b2l[idx] = bb;
        }
    } else if (b < 640) {
        // split: transpose + hi/lo split of w1 (first 256 blocks) / w2
        int gidx = (b - 128) * 256 + tid; // 0..131071
        int which = gidx >> 16;
        int idx = gidx & 65535;
        const float* w = which ? w2 : w1;
        __nv_bfloat16* Wh = which ? g_W2h : g_W1h;
        __nv_bfloat16* Wl = which ? g_W2l : g_W1l;
        int k = idx >> 8, n = idx & 255;
        float v = w[k * D_IN + n];
        __nv_bfloat16 hi = __float2bfloat16(v);
        Wh[n * D_IN + k] = hi;
        Wl[n * D_IN + k] = __float2bfloat16(v - __bfloat162float(hi));
    }

    // all blocks: zero g_h
    const size_t total = (size_t)N_NODES * D_IN / 4;
    float4* hs = (float4*)g_h;
    const float4 z = make_float4(0.f, 0.f, 0.f, 0.f);
    for (size_t i = (size_t)b * 256 + tid; i < total;
         i += (size_t)PREP_GRID * 256)
        hs[i] = z;
}

// ---------------- K2: edge kernel (64-edge tiles, 2 CTAs/SM) ----------------
// Proven R11 config: 1-term bf16 (Ah@Bh^T), permuted B, red.v4 epilogue.
#define STRIDE_AB 272
#define OFF_BH   0
#define OFF_A    69632
#define OFF_EW1  87040
#define OFF_RAW  95232
#define OFF_EB1  99328
#define OFF_B2L  99840
#define OFF_LEB  100864
#define OFF_POL  101888
#define OFF_SRC  102144
#define OFF_DST  102400
#define EDGE_SMEM 102656
#define EDGE_THREADS 256
#define EDGE_GRID 296

__global__ __launch_bounds__(EDGE_THREADS, 2)
void edge_kernel(const float* __restrict__ x,
                 const void* __restrict__ ei_raw,
                 const float* __restrict__ ea,
                 const float* __restrict__ ew1,
                 const float* __restrict__ eb1,
                 const float* __restrict__ leb) {
    extern __shared__ char smem[];
    const uint32_t smem_u = smem_to_u32(smem);
    float* s_ew1 = (float*)(smem + OFF_EW1);
    float* s_raw = (float*)(smem + OFF_RAW);
    float* s_eb1 = (float*)(smem + OFF_EB1);
    float* s_b2l = (float*)(smem + OFF_B2L);
    float* s_leb = (float*)(smem + OFF_LEB);
    float* s_pol = (float*)(smem + OFF_POL);
    int*   s_src = (int*)(smem + OFF_SRC);
    int*   s_dst = (int*)(smem + OFF_DST);

    const int tid = threadIdx.x;
    const int wid = tid >> 5;
    const int lane = tid & 31;
    const int is64 = g_is64;
    const long long* ei64 = (const long long*)ei_raw;
    const int*       ei32 = (const int*)ei_raw;

    for (int w = tid; w < 256 * 64; w += EDGE_THREADS) {
        int G = w >> 6, k2 = w & 63;
        int wnb = G >> 6;
        int gl = G & 63;
        int na = 2 * (gl >> 4) + ((gl >> 1) & 1);
        int c  = 2 * ((gl >> 2) & 3) + (gl & 1);
        int n  = wnb * 64 + na * 8 + c;
        *(uint32_t*)(smem + OFF_BH + (uint32_t)n * STRIDE_AB + (uint32_t)k2 * 4u)
            = ((const uint32_t*)g_Bh)[w];
    }
    for (int i = tid; i < D_RAW * D_HID; i += EDGE_THREADS) s_ew1[i] = ew1[i];
    if (tid < D_HID) s_eb1[tid] = eb1[tid];
    if (tid < D_IN) { s_b2l[tid] = g_b2l[tid]; s_leb[tid] = leb[tid]; }
    __syncthreads();

    const int numTiles = N_EDGES / TILE_E;
    const int stride = gridDim.x;

    const int wm = wid & 1;
    const int wn = wid >> 1;
    const uint32_t a_off = (uint32_t)(wm * 32 + (lane & 15)) * STRIDE_AB +
                           (uint32_t)(lane >> 4) * 16u;
    const uint32_t b4_off = (uint32_t)(wn * 64 + ((lane >> 4) & 1) * 8 +
                                       (lane & 7)) * STRIDE_AB +
                            (uint32_t)((lane >> 3) & 1) * 16u;
    const int q  = lane >> 2;

    for (int t = blockIdx.x; t < numTiles; t += stride) {
        {
            const int e0 = t * TILE_E;
            const int er0 = wid * 8;
            for (int i = lane; i < 8 * 17; i += 32) {
                int le = i / 17, c = i % 17;
                float v = ea[(size_t)(e0 + er0 + le) * 17 + c];
                if (c == 0)
                    s_pol[er0 + le] = fminf(fmaxf(v, 0.f), 1.f) + 0.01f;
                else
                    s_raw[(er0 + le) * D_RAW + (c - 1)] = v;
            }
            if (lane < 8) {
                int sv = is64 ? (int)ei64[e0 + er0 + lane]
                              : ei32[e0 + er0 + lane];
                s_src[er0 + lane] = min(max(sv, 0), N_NODES - 1);
            } else if (lane < 16) {
                int l8 = lane - 8;
                int dv = is64 ? (int)ei64[N_EDGES + e0 + er0 + l8]
                              : ei32[N_EDGES + e0 + er0 + l8];
                s_dst[er0 + l8] = min(max(dv, 0), N_NODES - 1);
            }
            __syncwarp();

            const int c0 = lane * 4;
            float4 a4[8];
            float4 eb4 = *(const float4*)&s_eb1[c0];
#pragma unroll
            for (int e = 0; e < 8; e++) a4[e] = eb4;
#pragma unroll
            for (int kb = 0; kb < 4; kb++) {
                float4 w0 = *(const float4*)&s_ew1[(kb * 4 + 0) * D_HID + c0];
                float4 w1 = *(const float4*)&s_ew1[(kb * 4 + 1) * D_HID + c0];
                float4 w2 = *(const float4*)&s_ew1[(kb * 4 + 2) * D_HID + c0];
                float4 w3 = *(const float4*)&s_ew1[(kb * 4 + 3) * D_HID + c0];
#pragma unroll
                for (int e = 0; e < 8; e++) {
                    float4 r = *(const float4*)&s_raw[(er0 + e) * D_RAW + kb * 4];
                    float4 a = a4[e];
                    a.x = fmaf(r.x, w0.x, a.x); a.y = fmaf(r.x, w0.y, a.y);
                    a.z = fmaf(r.x, w0.z, a.z); a.w = fmaf(r.x, w0.w, a.w);
                    a.x = fmaf(r.y, w1.x, a.x); a.y = fmaf(r.y, w1.y, a.y);
                    a.z = fmaf(r.y, w1.z, a.z); a.w = fmaf(r.y, w1.w, a.w);
                    a.x = fmaf(r.z, w2.x, a.x); a.y = fmaf(r.z, w2.y, a.y);
                    a.z = fmaf(r.z, w2.z, a.z); a.w = fmaf(r.z, w2.w, a.w);
                    a.x = fmaf(r.w, w3.x, a.x); a.y = fmaf(r.w, w3.y, a.y);
                    a.z = fmaf(r.w, w3.z, a.z); a.w = fmaf(r.w, w3.w, a.w);
                    a4[e] = a;
                }
            }
            char* ah = smem + OFF_A + (er0 * STRIDE_AB) + lane * 8;
#pragma unroll
            for (int e = 0; e < 8; e++) {
                float4 a = a4[e];
                __nv_bfloat162 h01, h23;
                h01.x = __float2bfloat16(fmaxf(a.x, 0.f));
                h01.y = __float2bfloat16(fmaxf(a.y, 0.f));
                h23.x = __float2bfloat16(fmaxf(a.z, 0.f));
                h23.y = __float2bfloat16(fmaxf(a.w, 0.f));
                *(uint2*)(ah + e * STRIDE_AB) =
                    make_uint2(*(uint32_t*)&h01, *(uint32_t*)&h23);
            }
        }
        __syncthreads();

        float acc[2][8][4];
#pragma unroll
        for (int ma = 0; ma < 2; ma++)
#pragma unroll
            for (int na = 0; na < 8; na++)
#pragma unroll
                for (int r = 0; r < 4; r++) acc[ma][na][r] = 0.f;

        const uint32_t aBase = smem_u + OFF_A;
#pragma unroll
        for (int ks = 0; ks < 8; ks++) {
            const uint32_t ka = (uint32_t)ks * 32u;
            uint32_t ah0[4], ah1[4];
            ldsm_x4(ah0, aBase + a_off + ka);
            ldsm_x4(ah1, aBase + a_off + 16u * STRIDE_AB + ka);
#pragma unroll
            for (int np = 0; np < 4; np++) {
                uint32_t bq[4];
                ldsm_x4(bq, smem_u + OFF_BH + b4_off +
                            (uint32_t)np * 16u * STRIDE_AB + ka);
                mma_bf16(acc[0][2 * np],     ah0, &bq[0]);
                mma_bf16(acc[1][2 * np],     ah1, &bq[0]);
                mma_bf16(acc[0][2 * np + 1], ah0, &bq[2]);
                mma_bf16(acc[1][2 * np + 1], ah1, &bq[2]);
            }
        }

#pragma unroll
        for (int ma = 0; ma < 2; ma++) {
#pragma unroll
            for (int hl = 0; hl < 2; hl++) {
                const int row = wm * 32 + ma * 16 + q + hl * 8;
                const float s = s_pol[row];
                const float* xr = x + (size_t)s_src[row] * D_IN + wn * 64;
                float* hd = g_h + (size_t)s_dst[row] * D_IN + wn * 64;
#pragma unroll
                for (int p = 0; p < 4; p++) {
                    const int cl = p * 16 + (lane & 3) * 4;
                    const int col = wn * 64 + cl;
                    float4 bb = *(const float4*)&s_b2l[col];
                    float4 ll = *(const float4*)&s_leb[col];
                    float4 xv = *(const float4*)(xr + cl);
                    float m0 = fmaxf(
                        fmaf(s, acc[ma][2 * p][hl * 2 + 0] + bb.x, ll.x) + xv.x,
                        0.f);
                    float m1 = fmaxf(
                        fmaf(s, acc[ma][2 * p][hl * 2 + 1] + bb.y, ll.y) + xv.y,
                        0.f);
                    float m2 = fmaxf(
                        fmaf(s, acc[ma][2 * p + 1][hl * 2 + 0] + bb.z, ll.z) +
                            xv.z, 0.f);
                    float m3 = fmaxf(
                        fmaf(s, acc[ma][2 * p + 1][hl * 2 + 1] + bb.w, ll.w) +
                            xv.w, 0.f);
                    red_v4(hd + cl, m0, m1, m2, m3);
                }
            }
        }
        __syncthreads();
    }
}

// ---------------- node GEMM kernels (HMMA, 3-term bf16 emulation) ----------
#define NOFF_BH   0          // B hi chunk [256n][272B]
#define NOFF_BL   69632
#define NOFF_AH   139264     // A hi chunk [128m][272B]
#define NOFF_AL   174080
#define NOFF_PART 208896     // [128][4][2] f32 partial sums (node1 LN)
#define NOFF_B    212992     // bias 256 f
#define NOFF_LNG  214016
#define NOFF_LNB  215040
#define NODE_SMEM 216064
#define N_TILES_M ((N_NODES + 127) / 128)   // 391

// WITH_LN also means: A = Asrc + Xadd (x folded into node1 staging).
template <bool WITH_LN>
__device__ __forceinline__ void node_gemm_body(
    const float* __restrict__ Asrc, const float* __restrict__ Xadd,
    const __nv_bfloat16* __restrict__ Wh,
    const __nv_bfloat16* __restrict__ Wl, const float* __restrict__ bias,
    const float* __restrict__ ln_g, const float* __restrict__ ln_b,
    float* __restrict__ Dst) {
    extern __shared__ char smem[];
    const uint32_t smem_u = smem_to_u32(smem);
    float* s_part = (float*)(smem + NOFF_PART);
    float* s_b    = (float*)(smem + NOFF_B);
    float* s_lng  = (float*)(smem + NOFF_LNG);
    float* s_lnb  = (float*)(smem + NOFF_LNB);

    const int tid = threadIdx.x;
    const int wid = tid >> 5;
    const int lane = tid & 31;
    const int r0 = blockIdx.x * 128;

    if (tid < D_IN) {
        s_b[tid] = bias[tid];
        if (WITH_LN) { s_lng[tid] = ln_g[tid]; s_lnb[tid] = ln_b[tid]; }
    }

    const int wm = wid & 3;
    const int wn = wid >> 2;
    const uint32_t a_off = (uint32_t)(wm * 32 + (lane & 15)) * STRIDE_AB +
                           (uint32_t)(lane >> 4) * 16u;
    const uint32_t b4_off = (uint32_t)(wn * 64 + ((lane >> 4) & 1) * 8 +
                                       (lane & 7)) * STRIDE_AB +
                            (uint32_t)((lane >> 3) & 1) * 16u;
    const int q  = lane >> 2;
    const int cp = (lane & 3) * 2;

    float acc[2][8][4];
#pragma unroll
    for (int ma = 0; ma < 2; ma++)
#pragma unroll
        for (int na = 0; na < 8; na++)
#pragma unroll
            for (int r = 0; r < 4; r++) acc[ma][na][r] = 0.f;

    for (int kc = 0; kc < 2; kc++) {
        for (int i = tid; i < 256 * 16; i += 512) {
            int n = i >> 4, c = i & 15;
            const size_t src = (size_t)n * D_IN + kc * 128 + c * 8;
            *(uint4*)(smem + NOFF_BH + (uint32_t)n * STRIDE_AB + c * 16) =
                *(const uint4*)(Wh + src);
            *(uint4*)(smem + NOFF_BL + (uint32_t)n * STRIDE_AB + c * 16) =
                *(const uint4*)(Wl + src);
        }
        for (int i = tid; i < 128 * 32; i += 512) {
            int r = i >> 5, c4 = i & 31;
            int rr = min(r0 + r, N_NODES - 1);
            const size_t src = (size_t)rr * D_IN + kc * 128 + c4 * 4;
            float4 v = *(const float4*)&Asrc[src];
            if (WITH_LN) {
                float4 xv = *(const float4*)&Xadd[src];
                v.x += xv.x; v.y += xv.y; v.z += xv.z; v.w += xv.w;
            }
            __nv_bfloat162 h01, h23, l01, l23;
            h01.x = __float2bfloat16(v.x); h01.y = __float2bfloat16(v.y);
            h23.x = __float2bfloat16(v.z); h23.y = __float2bfloat16(v.w);
            l01.x = __float2bfloat16(v.x - __bfloat162float(h01.x));
            l01.y = __float2bfloat16(v.y - __bfloat162float(h01.y));
            l23.x = __float2bfloat16(v.z - __bfloat162float(h23.x));
            l23.y = __float2bfloat16(v.w - __bfloat162float(h23.y));
            uint32_t off = (uint32_t)r * STRIDE_AB + c4 * 8;
            *(uint2*)(smem + NOFF_AH + off) =
                make_uint2(*(uint32_t*)&h01, *(uint32_t*)&h23);
            *(uint2*)(smem + NOFF_AL + off) =
                make_uint2(*(uint32_t*)&l01, *(uint32_t*)&l23);
        }
        __syncthreads();

#pragma unroll
        for (int ks = 0; ks < 8; ks++) {
            const uint32_t ka = (uint32_t)ks * 32u;
            uint32_t ah0[4], ah1[4], al0[4], al1[4];
            ldsm_x4(ah0, smem_u + NOFF_AH + a_off + ka);
            ldsm_x4(ah1, smem_u + NOFF_AH + a_off + 16u * STRIDE_AB + ka);
            ldsm_x4(al0, smem_u + NOFF_AL + a_off + ka);
            ldsm_x4(al1, smem_u + NOFF_AL + a_off + 16u * STRIDE_AB + ka);
#pragma unroll
            for (int np = 0; np < 4; np++) {
                uint32_t bh[4], bl[4];
                const uint32_t bo = b4_off + (uint32_t)np * 16u * STRIDE_AB + ka;
                ldsm_x4(bh, smem_u + NOFF_BH + bo);
                ldsm_x4(bl, smem_u + NOFF_BL + bo);
                mma_bf16(acc[0][2 * np],     ah0, &bh[0]);
                mma_bf16(acc[1][2 * np],     ah1, &bh[0]);
                mma_bf16(acc[0][2 * np],     al0, &bh[0]);
                mma_bf16(acc[1][2 * np],     al1, &bh[0]);
                mma_bf16(acc[0][2 * np],     ah0, &bl[0]);
                mma_bf16(acc[1][2 * np],     ah1, &bl[0]);
                mma_bf16(acc[0][2 * np + 1], ah0, &bh[2]);
                mma_bf16(acc[1][2 * np + 1], ah1, &bh[2]);
                mma_bf16(acc[0][2 * np + 1], al0, &bh[2]);
                mma_bf16(acc[1][2 * np + 1], al1, &bh[2]);
                mma_bf16(acc[0][2 * np + 1], ah0, &bl[2]);
                mma_bf16(acc[1][2 * np + 1], ah1, &bl[2]);
            }
        }
        __syncthreads();
    }

    float bcol[8][2];
#pragma unroll
    for (int na = 0; na < 8; na++) {
        bcol[na][0] = s_b[wn * 64 + na * 8 + cp];
        bcol[na][1] = s_b[wn * 64 + na * 8 + cp + 1];
    }
#pragma unroll
    for (int ma = 0; ma < 2; ma++)
#pragma unroll
        for (int na = 0; na < 8; na++)
#pragma unroll
            for (int hl = 0; hl < 2; hl++) {
                acc[ma][na][hl * 2 + 0] += bcol[na][0];
                acc[ma][na][hl * 2 + 1] += bcol[na][1];
            }

    if (WITH_LN) {
#pragma unroll
        for (int ma = 0; ma < 2; ma++)
#pragma unroll
            for (int hl = 0; hl < 2; hl++) {
                float s = 0.f, ss = 0.f;
#pragma unroll
                for (int na = 0; na < 8; na++) {
                    float v0 = acc[ma][na][hl * 2 + 0];
                    float v1 = acc[ma][na][hl * 2 + 1];
                    s += v0 + v1;
                    ss = fmaf(v0, v0, ss); ss = fmaf(v1, v1, ss);
                }
                s  += __shfl_xor_sync(0xffffffffu, s, 1);
                s  += __shfl_xor_sync(0xffffffffu, s, 2);
                ss += __shfl_xor_sync(0xffffffffu, ss, 1);
                ss += __shfl_xor_sync(0xffffffffu, ss, 2);
                if ((lane & 3) == 0) {
                    const int row = wm * 32 + ma * 16 + hl * 8 + q;
                    *(float2*)&s_part[row * 8 + wn * 2] = make_float2(s, ss);
                }
            }
        __syncthreads();

#pragma unroll
        for (int ma = 0; ma < 2; ma++)
#pragma unroll
            for (int hl = 0; hl < 2; hl++) {
                const int row = wm * 32 + ma * 16 + hl * 8 + q;
                float sum = 0.f, ssum = 0.f;
#pragma unroll
                for (int w = 0; w < 4; w++) {
                    float2 p = *(const float2*)&s_part[row * 8 + w * 2];
                    sum += p.x; ssum += p.y;
                }
                const float mu = sum * (1.f / D_IN);
                const float var =
                    fmaxf(ssum * (1.f / D_IN) - mu * mu, 0.f);
                const float rstd = rsqrtf(var + LN_EPS);
                const int grow = r0 + row;
                if (grow < N_NODES) {
#pragma unroll
                    for (int na = 0; na < 8; na++) {
                        const int col = wn * 64 + na * 8 + cp;
                        float g0 = s_lng[col], g1 = s_lng[col + 1];
                        float l0 = s_lnb[col], l1 = s_lnb[col + 1];
                        float o0 = fmaxf(
                            fmaf((acc[ma][na][hl * 2] - mu) * rstd, g0, l0), 0.f);
                        float o1 = fmaxf(
                            fmaf((acc[ma][na][hl * 2 + 1] - mu) * rstd, g1, l1),
                            0.f);
                        *(float2*)&Dst[(size_t)grow * D_IN + col] =
                            make_float2(o0, o1);
                    }
                }
            }
    } else {
#pragma unroll
        for (int ma = 0; ma < 2; ma++)
#pragma unroll
            for (int hl = 0; hl < 2; hl++) {
                const int row = wm * 32 + ma * 16 + hl * 8 + q;
                const int grow = r0 + row;
                if (grow < N_NODES) {
#pragma unroll
                    for (int na = 0; na < 8; na++) {
                        const int col = wn * 64 + na * 8 + cp;
                        *(float2*)&Dst[(size_t)grow * D_IN + col] =
                            make_float2(acc[ma][na][hl * 2],
                                        acc[ma][na][hl * 2 + 1]);
                    }
                }
            }
    }
}

__global__ __launch_bounds__(512, 1)
void node1_kernel(const float* __restrict__ x, const float* __restrict__ b1,
                  const float* __restrict__ ln_g,
                  const float* __restrict__ ln_b) {
    node_gemm_body<true>(g_h, x, g_W1h, g_W1l, b1, ln_g, ln_b, g_t);
}

__global__ __launch_bounds__(512, 1)
void node2_kernel(const float* __restrict__ b2, float* __restrict__ out) {
    node_gemm_body<false>(g_t, nullptr, g_W2h, g_W2l, b2, nullptr, nullptr, out);
}

// ---------------- launcher --------------------------------------------------
extern "C" void kernel_launch(void* const* d_in, const int* in_sizes, int n_in,
                              void* d_out, int out_size) {
    const float* x    = (const float*)d_in[0];
    const void*  ei   = d_in[1];
    const float* ea   = (const float*)d_in[2];
    const float* ew1  = (const float*)d_in[3];
    const float* eb1  = (const float*)d_in[4];
    const float* ew2  = (const float*)d_in[5];
    const float* eb2  = (const float*)d_in[6];
    const float* lew  = (const float*)d_in[7];
    const float* leb  = (const float*)d_in[8];
    const float* w1   = (const float*)d_in[9];
    const float* b1   = (const float*)d_in[10];
    const float* ln_g = (const float*)d_in[11];
    const float* ln_b = (const float*)d_in[12];
    const float* w2   = (const float*)d_in[13];
    const float* b2   = (const float*)d_in[14];
    float* out = (float*)d_out;

    cudaFuncSetAttribute(edge_kernel, cudaFuncAttributeMaxDynamicSharedMemorySize,
                         EDGE_SMEM);
    cudaFuncSetAttribute(node1_kernel, cudaFuncAttributeMaxDynamicSharedMemorySize,
                         NODE_SMEM);
    cudaFuncSetAttribute(node2_kernel, cudaFuncAttributeMaxDynamicSharedMemorySize,
                         NODE_SMEM);

    prep_kernel<<<PREP_GRID, 256>>>((const int*)ei, ew2, lew, eb2, w1, w2);
    edge_kernel<<<EDGE_GRID, EDGE_THREADS, EDGE_SMEM>>>(x, ei, ea, ew1, eb1, leb);
    node1_kernel<<<N_TILES_M, 512, NODE_SMEM>>>(x, b1, ln_g, ln_b);
    node2_kernel<<<N_TILES_M, 512, NODE_SMEM>>>(b2, out);
}